// round 2
// baseline (speedup 1.0000x reference)
#include <cuda_runtime.h>
#include <math.h>

#define B_    8
#define N_    4096
#define CIN   256
#define CQK   32
#define NROWS (B_ * N_)   // 32768

// ---- scratch (device globals; no allocation allowed) ----
__device__ float g_q[NROWS * CQK];      // 4 MB, row-major [row][c]
__device__ float g_kT[B_ * CQK * N_];   // 4 MB, transposed [b][c][m]
__device__ float g_vbar[NROWS];
__device__ float g_xbar[NROWS];
__device__ float g_wvbar[CIN];
__device__ float g_bvbar;

// ---- helpers ----
__device__ __forceinline__ void cp_async16(void* dst, const void* src) {
    unsigned d = (unsigned)__cvta_generic_to_shared(dst);
    asm volatile("cp.async.cg.shared.global [%0], [%1], 16;" :: "r"(d), "l"(src) : "memory");
}
__device__ __forceinline__ void cp_commit() {
    asm volatile("cp.async.commit_group;" ::: "memory");
}
__device__ __forceinline__ unsigned long long pack2(float v) {
    unsigned long long r;
    asm("mov.b64 %0, {%1, %1};" : "=l"(r) : "f"(v));
    return r;
}
__device__ __forceinline__ void fma2(unsigned long long& d,
                                     unsigned long long a, unsigned long long b) {
    asm("fma.rn.f32x2 %0, %1, %2, %0;" : "+l"(d) : "l"(a), "l"(b));
}
__device__ __forceinline__ void unpack2(unsigned long long v, float& lo, float& hi) {
    asm("mov.b64 {%0, %1}, %2;" : "=f"(lo), "=f"(hi) : "l"(v));
}

// ---------------------------------------------------------------------------
// Kernel 0: wv_bar[i] = mean_j Wv[i,j];  bvbar = mean(bv)
// ---------------------------------------------------------------------------
__global__ void prep_kernel(const float* __restrict__ Wv,
                            const float* __restrict__ bv) {
    int i = threadIdx.x;          // 256 threads
    float s = 0.f;
    #pragma unroll 4
    for (int j = 0; j < CIN; j++) s += Wv[i * CIN + j];
    g_wvbar[i] = s * (1.f / CIN);
    if (i == 0) {
        float t = 0.f;
        for (int j = 0; j < CIN; j++) t += bv[j];
        g_bvbar = t * (1.f / CIN);
    }
}

// ---------------------------------------------------------------------------
// Kernel 1: fused Q/K projection GEMM with FFMA2 inner loop.
//   C(32768 x 64) = x(32768 x 256) @ [Wq | Wk](256 x 64), + bias.
//   Q stored row-major to g_q; K stored TRANSPOSED to g_kT via smem staging.
//   Tile 128 x 64, K-tile 32. 256 threads (16x16), 8x4 micro-tile each.
// ---------------------------------------------------------------------------
__global__ __launch_bounds__(256) void qk_gemm(
    const float* __restrict__ x,
    const float* __restrict__ Wq, const float* __restrict__ bq,
    const float* __restrict__ Wk, const float* __restrict__ bk) {

    __shared__ __align__(16) float As[128][36];
    __shared__ __align__(16) float Bs[32][64];
    __shared__ __align__(16) float kT_s[32][128];

    const int tid = threadIdx.x;
    const int tx = tid & 15, ty = tid >> 4;
    const int m0 = blockIdx.x * 128;

    unsigned long long acc2[8][2];
    #pragma unroll
    for (int i = 0; i < 8; i++) { acc2[i][0] = 0ull; acc2[i][1] = 0ull; }

    for (int kt = 0; kt < CIN; kt += 32) {
        // load A tile: 128 x 32 of x
        {
            int c4 = tid & 7, r0 = tid >> 3;
            #pragma unroll
            for (int p = 0; p < 4; p++) {
                int r = r0 + p * 32;
                *(float4*)(&As[r][c4 * 4]) =
                    *(const float4*)(x + (size_t)(m0 + r) * CIN + kt + c4 * 4);
            }
        }
        // load B tile: 32 x 64 ([Wq | Wk])
        {
            int c4 = tid & 15, r0 = tid >> 4;
            #pragma unroll
            for (int p = 0; p < 2; p++) {
                int r = r0 + p * 16;
                float4 v;
                if (c4 < 8) v = *(const float4*)(Wq + (size_t)(kt + r) * CQK + c4 * 4);
                else        v = *(const float4*)(Wk + (size_t)(kt + r) * CQK + (c4 - 8) * 4);
                *(float4*)(&Bs[r][c4 * 4]) = v;
            }
        }
        __syncthreads();

        #pragma unroll
        for (int k4 = 0; k4 < 8; k4++) {
            float4 a4[8];
            #pragma unroll
            for (int i = 0; i < 8; i++) a4[i] = *(const float4*)(&As[ty * 8 + i][k4 * 4]);
            #pragma unroll
            for (int kc = 0; kc < 4; kc++) {
                ulonglong2 b2 = *(const ulonglong2*)(&Bs[k4 * 4 + kc][tx * 4]);
                #pragma unroll
                for (int i = 0; i < 8; i++) {
                    float av = (kc == 0) ? a4[i].x : (kc == 1) ? a4[i].y
                             : (kc == 2) ? a4[i].z : a4[i].w;
                    unsigned long long aa = pack2(av);
                    fma2(acc2[i][0], aa, b2.x);
                    fma2(acc2[i][1], aa, b2.y);
                }
            }
        }
        __syncthreads();
    }

    // epilogue
    const int c = tx * 4;
    if (c < 32) {
        float4 bb = *(const float4*)(bq + c);
        #pragma unroll
        for (int i = 0; i < 8; i++) {
            float l0, h0, l1, h1;
            unpack2(acc2[i][0], l0, h0);
            unpack2(acc2[i][1], l1, h1);
            float4 o = { l0 + bb.x, h0 + bb.y, l1 + bb.z, h1 + bb.w };
            *(float4*)(g_q + (size_t)(m0 + ty * 8 + i) * CQK + c) = o;
        }
    } else {
        float4 bb = *(const float4*)(bk + c - 32);
        int c0 = c - 32;
        #pragma unroll
        for (int i = 0; i < 8; i++) {
            float l0, h0, l1, h1;
            unpack2(acc2[i][0], l0, h0);
            unpack2(acc2[i][1], l1, h1);
            int ml = ty * 8 + i;
            kT_s[c0 + 0][ml] = l0 + bb.x;
            kT_s[c0 + 1][ml] = h0 + bb.y;
            kT_s[c0 + 2][ml] = l1 + bb.z;
            kT_s[c0 + 3][ml] = h1 + bb.w;
        }
    }
    __syncthreads();

    // coalesced transposed K write-out
    {
        const int b   = m0 >> 12;
        const int mloc = m0 & (N_ - 1);
        int cc = tid >> 3, col = (tid & 7) * 16;
        #pragma unroll
        for (int q = 0; q < 4; q++) {
            *(float4*)(g_kT + ((size_t)b * CQK + cc) * N_ + mloc + col + q * 4) =
                *(const float4*)(&kT_s[cc][col + q * 4]);
        }
    }
}

// ---------------------------------------------------------------------------
// Kernel 2: per-row vbar / xbar. One warp per row.
// ---------------------------------------------------------------------------
__global__ __launch_bounds__(256) void vx_kernel(const float* __restrict__ x) {
    const int warp = threadIdx.x >> 5, lane = threadIdx.x & 31;
    const size_t row = (size_t)blockIdx.x * 8 + warp;
    const float* xr = x + row * CIN;
    float sv = 0.f, sx = 0.f;
    #pragma unroll
    for (int j = 0; j < 8; j++) {
        float xv = xr[lane + j * 32];
        sv += xv * g_wvbar[lane + j * 32];
        sx += xv;
    }
    #pragma unroll
    for (int off = 16; off > 0; off >>= 1) {
        sv += __shfl_xor_sync(0xffffffffu, sv, off);
        sx += __shfl_xor_sync(0xffffffffu, sx, off);
    }
    if (lane == 0) {
        g_vbar[row] = sv + g_bvbar;
        g_xbar[row] = sx * (1.f / CIN);
    }
}

// ---------------------------------------------------------------------------
// Kernel 3: fused attention with FFMA2 Q@K^T, exp-without-max softmax over the
//   collapsed scalar value vbar. Double-buffered cp.async K chunks.
//   Block 256 = 16x16: ty owns 4 q-rows (64-row q tile), tx owns 8 m-cols of
//   each 128-key chunk (4 adjacent column-pairs -> f32x2 lanes).
// ---------------------------------------------------------------------------
__global__ __launch_bounds__(256) void attn_kernel(
    const float* __restrict__ gamma, float* __restrict__ out) {

    __shared__ __align__(16) float q_s[64][36];
    __shared__ __align__(16) float k_s[2][32][128];
    __shared__ __align__(16) float vb_s[2][128];

    const int b  = blockIdx.y;
    const int n0 = blockIdx.x * 64;
    const int tid = threadIdx.x;
    const int tx = tid & 15, ty = tid >> 4;

    // q tile (64 x 32)
    {
        const float* qb = g_q + ((size_t)b * N_ + n0) * CQK;
        int c4 = tid & 7, r0 = tid >> 3;
        #pragma unroll
        for (int p = 0; p < 2; p++) {
            int r = r0 + p * 32;
            *(float4*)(&q_s[r][c4 * 4]) = *(const float4*)(qb + (size_t)r * CQK + c4 * 4);
        }
    }

    const int   lc   = tid >> 3;          // 0..31: k row to fetch
    const int   lcol = (tid & 7) * 16;    // col base within chunk
    const float* kT_b = g_kT + (size_t)b * CQK * N_;
    const float* vb_b = g_vbar + (size_t)b * N_;

    // prologue: chunk 0
    {
        const float* src = kT_b + (size_t)lc * N_ + lcol;
        #pragma unroll
        for (int q = 0; q < 4; q++) cp_async16(&k_s[0][lc][lcol + q * 4], src + q * 4);
        if (tid < 32) cp_async16(&vb_s[0][tid * 4], vb_b + tid * 4);
        cp_commit();
    }

    float den[4] = {0.f, 0.f, 0.f, 0.f};
    float num[4] = {0.f, 0.f, 0.f, 0.f};

    for (int ci = 0; ci < N_ / 128; ci++) {
        const int buf = ci & 1;
        if (ci + 1 < N_ / 128) {
            const int nb = (ci + 1) & 1;
            const float* src = kT_b + (size_t)lc * N_ + (ci + 1) * 128 + lcol;
            #pragma unroll
            for (int q = 0; q < 4; q++) cp_async16(&k_s[nb][lc][lcol + q * 4], src + q * 4);
            if (tid < 32) cp_async16(&vb_s[nb][tid * 4], vb_b + (ci + 1) * 128 + tid * 4);
            cp_commit();
            asm volatile("cp.async.wait_group 1;" ::: "memory");
        } else {
            asm volatile("cp.async.wait_group 0;" ::: "memory");
        }
        __syncthreads();

        unsigned long long acc2[4][4];
        #pragma unroll
        for (int i = 0; i < 4; i++)
            #pragma unroll
            for (int p = 0; p < 4; p++) acc2[i][p] = 0ull;

        #pragma unroll
        for (int c4 = 0; c4 < 8; c4++) {
            float4 q4[4];
            #pragma unroll
            for (int i = 0; i < 4; i++)
                q4[i] = *(const float4*)(&q_s[ty * 4 + i][c4 * 4]);
            #pragma unroll
            for (int cc = 0; cc < 4; cc++) {
                const float* krow = &k_s[buf][c4 * 4 + cc][tx * 8];
                ulonglong2 ka = *(const ulonglong2*)(krow);
                ulonglong2 kb = *(const ulonglong2*)(krow + 4);
                #pragma unroll
                for (int i = 0; i < 4; i++) {
                    float qv = (cc == 0) ? q4[i].x : (cc == 1) ? q4[i].y
                             : (cc == 2) ? q4[i].z : q4[i].w;
                    unsigned long long qq = pack2(qv);
                    fma2(acc2[i][0], qq, ka.x);
                    fma2(acc2[i][1], qq, ka.y);
                    fma2(acc2[i][2], qq, kb.x);
                    fma2(acc2[i][3], qq, kb.y);
                }
            }
        }

        // epilogue: exp + running sums (no max tracking: |energy| << 88)
        float vbl[4], vbh[4];
        #pragma unroll
        for (int p = 0; p < 4; p++) {
            vbl[p] = vb_s[buf][tx * 8 + 2 * p];
            vbh[p] = vb_s[buf][tx * 8 + 2 * p + 1];
        }
        #pragma unroll
        for (int i = 0; i < 4; i++) {
            #pragma unroll
            for (int p = 0; p < 4; p++) {
                float lo, hi;
                unpack2(acc2[i][p], lo, hi);
                float el = __expf(lo), eh = __expf(hi);
                den[i] += el + eh;
                num[i] = fmaf(el, vbl[p], fmaf(eh, vbh[p], num[i]));
            }
        }
        __syncthreads();
    }

    // merge across the 16 tx lanes sharing each q-row (offsets stay in half-warp)
    const float g = gamma[0];
    #pragma unroll
    for (int i = 0; i < 4; i++) {
        float si = den[i], ni = num[i];
        #pragma unroll
        for (int off = 1; off < 16; off <<= 1) {
            si += __shfl_xor_sync(0xffffffffu, si, off);
            ni += __shfl_xor_sync(0xffffffffu, ni, off);
        }
        if (tx == 0) {
            size_t idx = (size_t)b * N_ + n0 + ty * 4 + i;
            out[idx] = g * (ni / si) + g_xbar[idx];
        }
    }
}

// ---------------------------------------------------------------------------
extern "C" void kernel_launch(void* const* d_in, const int* in_sizes, int n_in,
                              void* d_out, int out_size) {
    const float* x     = (const float*)d_in[0];
    const float* Wq    = (const float*)d_in[1];
    const float* bq    = (const float*)d_in[2];
    const float* Wk    = (const float*)d_in[3];
    const float* bk    = (const float*)d_in[4];
    const float* Wv    = (const float*)d_in[5];
    const float* bv    = (const float*)d_in[6];
    const float* gamma = (const float*)d_in[7];
    float* out = (float*)d_out;

    prep_kernel<<<1, 256>>>(Wv, bv);
    qk_gemm<<<NROWS / 128, 256>>>(x, Wq, bq, Wk, bk);
    vx_kernel<<<NROWS / 8, 256>>>(x);
    attn_kernel<<<dim3(N_ / 64, B_), 256>>>(gamma, out);
}

// round 4
// speedup vs baseline: 2.2538x; 2.2538x over previous
#include <cuda_runtime.h>
#include <cuda_bf16.h>
#include <math.h>
#include <stdint.h>

#define B_    8
#define N_    4096
#define CIN   256
#define CQK   32
#define NROWS (B_ * N_)   // 32768
#define KSPL  96          // split-K: [hi|lo|hi] x [hi|hi|lo]
#define NCHUNK (N_ / 128) // 32

// ---- scratch (device globals; no allocation allowed) ----
__device__ __nv_bfloat16 g_qs[NROWS * KSPL];   // 6 MB  [row][96]
__device__ __nv_bfloat16 g_ks[NROWS * KSPL];   // 6 MB  [row][96]
__device__ float g_vbar[NROWS];
__device__ float g_xbar[NROWS];
__device__ float g_wvbar[CIN];
__device__ float g_bvbar;

// =========================== PTX helpers ===================================
__device__ __forceinline__ uint32_t smem_u32(const void* p) {
    uint32_t a;
    asm("{ .reg .u64 t; cvta.to.shared.u64 t, %1; cvt.u32.u64 %0, t; }"
        : "=r"(a) : "l"(p));
    return a;
}
__device__ __forceinline__ void cp_async16(void* dst, const void* src) {
    uint32_t d = smem_u32(dst);
    asm volatile("cp.async.cg.shared.global [%0], [%1], 16;" :: "r"(d), "l"(src) : "memory");
}
#define CP_COMMIT()  asm volatile("cp.async.commit_group;" ::: "memory")
#define CP_WAIT(n)   asm volatile("cp.async.wait_group %0;" :: "n"(n) : "memory")

__device__ __forceinline__ void ldsm_x4(uint32_t& r0, uint32_t& r1,
                                        uint32_t& r2, uint32_t& r3, uint32_t a) {
    asm volatile("ldmatrix.sync.aligned.m8n8.x4.shared.b16 {%0,%1,%2,%3}, [%4];"
        : "=r"(r0), "=r"(r1), "=r"(r2), "=r"(r3) : "r"(a));
}
__device__ __forceinline__ void mma_bf16(float& d0, float& d1, float& d2, float& d3,
    uint32_t a0, uint32_t a1, uint32_t a2, uint32_t a3,
    uint32_t b0, uint32_t b1,
    float c0, float c1, float c2, float c3) {
    asm volatile("mma.sync.aligned.m16n8k16.row.col.f32.bf16.bf16.f32 "
        "{%0,%1,%2,%3},{%4,%5,%6,%7},{%8,%9},{%10,%11,%12,%13};"
        : "=f"(d0), "=f"(d1), "=f"(d2), "=f"(d3)
        : "r"(a0), "r"(a1), "r"(a2), "r"(a3), "r"(b0), "r"(b1),
          "f"(c0), "f"(c1), "f"(c2), "f"(c3));
}

// =========================== small kernels =================================
__global__ void prep_kernel(const float* __restrict__ Wv,
                            const float* __restrict__ bv) {
    int i = threadIdx.x;
    float s = 0.f;
    #pragma unroll 4
    for (int j = 0; j < CIN; j++) s += Wv[i * CIN + j];
    g_wvbar[i] = s * (1.f / CIN);
    if (i == 0) {
        float t = 0.f;
        for (int j = 0; j < CIN; j++) t += bv[j];
        g_bvbar = t * (1.f / CIN);
    }
}

__global__ __launch_bounds__(256) void vx_kernel(const float* __restrict__ x) {
    const int warp = threadIdx.x >> 5, lane = threadIdx.x & 31;
    const size_t row = (size_t)blockIdx.x * 8 + warp;
    const float* xr = x + row * CIN;
    float sv = 0.f, sx = 0.f;
    #pragma unroll
    for (int j = 0; j < 8; j++) {
        float xv = xr[lane + j * 32];
        sv += xv * g_wvbar[lane + j * 32];
        sx += xv;
    }
    #pragma unroll
    for (int off = 16; off > 0; off >>= 1) {
        sv += __shfl_xor_sync(0xffffffffu, sv, off);
        sx += __shfl_xor_sync(0xffffffffu, sx, off);
    }
    if (lane == 0) {
        g_vbar[row] = sv + g_bvbar;
        g_xbar[row] = sx * (1.f / CIN);
    }
}

// ======================= Q/K projection GEMM ===============================
// C(32768 x 64) = x(32768 x 256) @ [Wq|Wk](256 x 64) + bias.
// Epilogue writes bf16 hi/lo splits: g_qs=[hi|lo|hi], g_ks=[hi|hi|lo].
__device__ __forceinline__ uint32_t pack_bf2(float a, float b) {
    __nv_bfloat162 t = __floats2bfloat162_rn(a, b);
    return *reinterpret_cast<uint32_t*>(&t);
}

__global__ __launch_bounds__(256) void qk_gemm(
    const float* __restrict__ x,
    const float* __restrict__ Wq, const float* __restrict__ bq,
    const float* __restrict__ Wk, const float* __restrict__ bk) {

    __shared__ __align__(16) float As[128][36];
    __shared__ __align__(16) float Bs[32][64];

    const int tid = threadIdx.x;
    const int tx = tid & 15, ty = tid >> 4;
    const int m0 = blockIdx.x * 128;

    float acc[8][4];
    #pragma unroll
    for (int i = 0; i < 8; i++)
        #pragma unroll
        for (int j = 0; j < 4; j++) acc[i][j] = 0.f;

    for (int kt = 0; kt < CIN; kt += 32) {
        {
            int c4 = tid & 7, r0 = tid >> 3;
            #pragma unroll
            for (int p = 0; p < 4; p++) {
                int r = r0 + p * 32;
                *(float4*)(&As[r][c4 * 4]) =
                    *(const float4*)(x + (size_t)(m0 + r) * CIN + kt + c4 * 4);
            }
        }
        {
            int c4 = tid & 15, r0 = tid >> 4;
            #pragma unroll
            for (int p = 0; p < 2; p++) {
                int r = r0 + p * 16;
                float4 v;
                if (c4 < 8) v = *(const float4*)(Wq + (size_t)(kt + r) * CQK + c4 * 4);
                else        v = *(const float4*)(Wk + (size_t)(kt + r) * CQK + (c4 - 8) * 4);
                *(float4*)(&Bs[r][c4 * 4]) = v;
            }
        }
        __syncthreads();

        #pragma unroll
        for (int kk = 0; kk < 32; kk++) {
            float a[8];
            #pragma unroll
            for (int i = 0; i < 8; i++) a[i] = As[ty * 8 + i][kk];
            float4 bv4 = *(const float4*)(&Bs[kk][tx * 4]);
            #pragma unroll
            for (int i = 0; i < 8; i++) {
                acc[i][0] += a[i] * bv4.x;
                acc[i][1] += a[i] * bv4.y;
                acc[i][2] += a[i] * bv4.z;
                acc[i][3] += a[i] * bv4.w;
            }
        }
        __syncthreads();
    }

    const int c = tx * 4;
    const bool isQ = (c < 32);
    const int c0 = isQ ? c : c - 32;
    float4 bb = isQ ? *(const float4*)(bq + c0) : *(const float4*)(bk + c0);

    #pragma unroll
    for (int i = 0; i < 8; i++) {
        size_t row = (size_t)m0 + ty * 8 + i;
        float v0 = acc[i][0] + bb.x, v1 = acc[i][1] + bb.y;
        float v2 = acc[i][2] + bb.z, v3 = acc[i][3] + bb.w;
        __nv_bfloat16 h0 = __float2bfloat16_rn(v0), h1 = __float2bfloat16_rn(v1);
        __nv_bfloat16 h2 = __float2bfloat16_rn(v2), h3 = __float2bfloat16_rn(v3);
        float l0 = v0 - __bfloat162float(h0), l1 = v1 - __bfloat162float(h1);
        float l2 = v2 - __bfloat162float(h2), l3 = v3 - __bfloat162float(h3);
        uint2 hi = make_uint2(pack_bf2(v0, v1), pack_bf2(v2, v3));
        uint2 lo = make_uint2(pack_bf2(l0, l1), pack_bf2(l2, l3));
        if (isQ) {
            __nv_bfloat16* dst = g_qs + row * KSPL + c0;
            *(uint2*)(dst)      = hi;   // q_hi
            *(uint2*)(dst + 32) = lo;   // q_lo
            *(uint2*)(dst + 64) = hi;   // q_hi
        } else {
            __nv_bfloat16* dst = g_ks + row * KSPL + c0;
            *(uint2*)(dst)      = hi;   // k_hi
            *(uint2*)(dst + 32) = hi;   // k_hi
            *(uint2*)(dst + 64) = lo;   // k_lo
        }
    }
}

// =========================== attention kernel ==============================
// smem tiles: [128 rows][104 bf16] (208-B pitch -> conflict-free ldmatrix)
#define TPITCH   208
#define TILE_B   (128 * TPITCH)      // 26624
#define OFF_VB   0                   // 16 KB vbar
#define OFF_Q    16384
#define OFF_K0   (OFF_Q + TILE_B)    // 43008
#define OFF_K1   (OFF_K0 + TILE_B)   // 69632
#define SMEM_TOT (OFF_K1 + TILE_B)   // 96256

__global__ __launch_bounds__(256) void attn_kernel(
    const float* __restrict__ gamma, float* __restrict__ out) {

    extern __shared__ __align__(16) char smem[];
    const uint32_t sb = smem_u32(smem);
    const int tid = threadIdx.x, wid = tid >> 5, lane = tid & 31;
    const int b = blockIdx.y, n0 = blockIdx.x * 128;

    // per-thread cp.async offsets for a 128x96 bf16 tile (1536 16B segs, 6/thread)
    int boff[6]; long soff[6];
    #pragma unroll
    for (int t = 0; t < 6; t++) {
        int idx = tid + t * 256;
        int row = idx / 12, seg = idx % 12;
        boff[t] = row * TPITCH + seg * 16;
        soff[t] = (long)row * KSPL + seg * 8;
    }

    const __nv_bfloat16* qsrc = g_qs + ((size_t)b * N_ + n0) * KSPL;
    const __nv_bfloat16* ksrc = g_ks + (size_t)b * N_ * KSPL;

    // prologue: group0 = VB + Q + K0 ; group1 = K1
    #pragma unroll
    for (int t = 0; t < 4; t++)
        cp_async16(smem + OFF_VB + (tid + t * 256) * 16,
                   g_vbar + (size_t)b * N_ + (tid + t * 256) * 4);
    #pragma unroll
    for (int t = 0; t < 6; t++) cp_async16(smem + OFF_Q + boff[t], qsrc + soff[t]);
    #pragma unroll
    for (int t = 0; t < 6; t++) cp_async16(smem + OFF_K0 + boff[t], ksrc + soff[t]);
    CP_COMMIT();
    #pragma unroll
    for (int t = 0; t < 6; t++)
        cp_async16(smem + OFF_K1 + boff[t], ksrc + (size_t)128 * KSPL + soff[t]);
    CP_COMMIT();

    uint32_t A[6][4];                      // persistent q fragments (16 rows x 96 k)
    float den0 = 0.f, den1 = 0.f, num0 = 0.f, num1 = 0.f;
    const float* vbp = (const float*)(smem + OFF_VB);

    // B-operand ldmatrix base for this lane (row within 8, 16B col group)
    const uint32_t kb_lane = (uint32_t)((lane & 7) * TPITCH + (lane >> 3) * 16);

    for (int ci = 0; ci < NCHUNK; ci++) {
        if (ci == NCHUNK - 1) { CP_WAIT(0); } else { CP_WAIT(1); }
        __syncthreads();

        if (ci == 0) {
            // load A fragments once: rows wid*16..+15, 6 k-steps of 16
            uint32_t qa = sb + OFF_Q + (wid * 16 + (lane & 15)) * TPITCH + (lane >> 4) * 16;
            #pragma unroll
            for (int s = 0; s < 6; s++)
                ldsm_x4(A[s][0], A[s][1], A[s][2], A[s][3], qa + s * 32);
        }

        const uint32_t kbase = sb + ((ci & 1) ? OFF_K1 : OFF_K0) + kb_lane;
        const float* vb = vbp + ci * 128 + (lane & 3) * 2;

        #pragma unroll
        for (int j = 0; j < 16; j++) {
            uint32_t b0, b1, b2, b3, b4, b5, b6, b7, b8, b9, b10, b11;
            uint32_t a = kbase + j * (8 * TPITCH);
            ldsm_x4(b0, b1, b2, b3, a);          // k 0..31
            ldsm_x4(b4, b5, b6, b7, a + 64);     // k 32..63
            ldsm_x4(b8, b9, b10, b11, a + 128);  // k 64..95

            float d0, d1, d2, d3;
            mma_bf16(d0, d1, d2, d3, A[0][0], A[0][1], A[0][2], A[0][3], b0, b1,
                     0.f, 0.f, 0.f, 0.f);
            mma_bf16(d0, d1, d2, d3, A[1][0], A[1][1], A[1][2], A[1][3], b2, b3,
                     d0, d1, d2, d3);
            mma_bf16(d0, d1, d2, d3, A[2][0], A[2][1], A[2][2], A[2][3], b4, b5,
                     d0, d1, d2, d3);
            mma_bf16(d0, d1, d2, d3, A[3][0], A[3][1], A[3][2], A[3][3], b6, b7,
                     d0, d1, d2, d3);
            mma_bf16(d0, d1, d2, d3, A[4][0], A[4][1], A[4][2], A[4][3], b8, b9,
                     d0, d1, d2, d3);
            mma_bf16(d0, d1, d2, d3, A[5][0], A[5][1], A[5][2], A[5][3], b10, b11,
                     d0, d1, d2, d3);

            // epilogue: cols j*8 + (lane&3)*2 + {0,1}; rows lane/4, lane/4+8
            float2 vv = *(const float2*)(vb + j * 8);
            float e0 = __expf(d0), e1 = __expf(d1);
            float e2 = __expf(d2), e3 = __expf(d3);
            den0 += e0 + e1;
            num0 = fmaf(e0, vv.x, fmaf(e1, vv.y, num0));
            den1 += e2 + e3;
            num1 = fmaf(e2, vv.x, fmaf(e3, vv.y, num1));
        }

        __syncthreads();
        if (ci + 2 < NCHUNK) {   // refill the buffer chunk ci just finished with
            char* dst = smem + ((ci & 1) ? OFF_K1 : OFF_K0);
            const __nv_bfloat16* src = ksrc + (size_t)(ci + 2) * 128 * KSPL;
            #pragma unroll
            for (int t = 0; t < 6; t++) cp_async16(dst + boff[t], src + soff[t]);
            CP_COMMIT();
        }
    }

    // reduce across the 4 lanes of each quad (they share the same rows)
    #pragma unroll
    for (int off = 1; off < 4; off <<= 1) {
        den0 += __shfl_xor_sync(0xffffffffu, den0, off);
        num0 += __shfl_xor_sync(0xffffffffu, num0, off);
        den1 += __shfl_xor_sync(0xffffffffu, den1, off);
        num1 += __shfl_xor_sync(0xffffffffu, num1, off);
    }
    if ((lane & 3) == 0) {
        const float g = gamma[0];
        int r0 = n0 + wid * 16 + (lane >> 2);
        size_t i0 = (size_t)b * N_ + r0;
        size_t i1 = i0 + 8;
        out[i0] = g * (num0 / den0) + g_xbar[i0];
        out[i1] = g * (num1 / den1) + g_xbar[i1];
    }
}

// ---------------------------------------------------------------------------
extern "C" void kernel_launch(void* const* d_in, const int* in_sizes, int n_in,
                              void* d_out, int out_size) {
    const float* x     = (const float*)d_in[0];
    const float* Wq    = (const float*)d_in[1];
    const float* bq    = (const float*)d_in[2];
    const float* Wk    = (const float*)d_in[3];
    const float* bk    = (const float*)d_in[4];
    const float* Wv    = (const float*)d_in[5];
    const float* bv    = (const float*)d_in[6];
    const float* gamma = (const float*)d_in[7];
    float* out = (float*)d_out;

    prep_kernel<<<1, 256>>>(Wv, bv);
    qk_gemm<<<NROWS / 128, 256>>>(x, Wq, bq, Wk, bk);
    vx_kernel<<<NROWS / 8, 256>>>(x);

    cudaFuncSetAttribute(attn_kernel, cudaFuncAttributeMaxDynamicSharedMemorySize, SMEM_TOT);
    attn_kernel<<<dim3(N_ / 128, B_), 256, SMEM_TOT>>>(gamma, out);
}